// round 8
// baseline (speedup 1.0000x reference)
#include <cuda_runtime.h>
#include <cuda_bf16.h>

// Problem: o [N=16, C=32, D=32, H=64, W=64] fp32, bias [C] fp32.
// out[n] = (1/(2*16384)) * sum_{c, pooled cells} max_{2x2x2}(o) + sum_c bias_c
// Pure HBM-streaming reduction: 256 MB in, 64 B out.
//
// Single-wave version: 1024 blocks (64 per n), each streams 8 contiguous
// (c,pd) slabs = 256 KB, one atomic epilogue per block. "Last block per n"
// finishes the reduction, adds the bias sum, writes out[n], and resets the
// persistent scratch (graph-replay safe).

#define N_  16
#define C_  32
#define D_  32
#define H_  64
#define W_  64
#define PD_ (D_/2)
#define SLABS_PER_N   (C_ * PD_)      // 512
#define BLOCKS_PER_N  64
#define SLABS_PER_BLK (SLABS_PER_N / BLOCKS_PER_N)   // 8
// scale = 1/DIVISOR * 1/(PD*PH*PW) = 1/2 * 1/16384
#define SCALE_ (1.0f / 32768.0f)

// Persistent scratch (zero-initialized at module load; reset by last block
// every call, so every launch sees zeros).
__device__ float        g_scratch[N_];
__device__ unsigned int g_count[N_];

__global__ __launch_bounds__(256, 8)
void fused_pool_reduce_kernel(const float* __restrict__ o,
                              const float* __restrict__ bias,
                              float* __restrict__ out) {
    const int x   = blockIdx.x;   // 0..63 : chunk of 8 slabs within n
    const int n   = blockIdx.y;   // 0..15
    const int tid = threadIdx.x;  // 0..255

    // Slabs s = x*8 .. x*8+7; slab s -> c = s>>4, pd = s&15.
    // The 8 slabs are contiguous in memory: one 256 KB region.
    const int s0 = x * SLABS_PER_BLK;
    // Base address of first slab: ((n*C + c)*D + 2*pd) * H*W
    const size_t slab_elems = (size_t)2 * H_ * W_;   // 8192 floats per slab
    const float* base0 = o + (((size_t)n * C_ + (s0 >> 4)) * D_ + 2 * (s0 & 15)) * (H_ * W_);

    // Per-slab work items: PH(32) x (W/4=16) = 512 tiles; 256 threads -> 2 each.
    const int item0 = tid;
    const int item1 = tid + 256;
    const int r0 = ((item0 >> 4) * 2) * W_ + (item0 & 15) * 4;
    const int r1 = ((item1 >> 4) * 2) * W_ + (item1 & 15) * 4;

    float acc = 0.0f;
    #pragma unroll
    for (int s = 0; s < SLABS_PER_BLK; ++s) {
        const float* base = base0 + s * slab_elems;

        const float4 a00 = *reinterpret_cast<const float4*>(base + r0);
        const float4 a01 = *reinterpret_cast<const float4*>(base + r0 + W_);
        const float4 a02 = *reinterpret_cast<const float4*>(base + r0 + H_ * W_);
        const float4 a03 = *reinterpret_cast<const float4*>(base + r0 + H_ * W_ + W_);
        const float4 a10 = *reinterpret_cast<const float4*>(base + r1);
        const float4 a11 = *reinterpret_cast<const float4*>(base + r1 + W_);
        const float4 a12 = *reinterpret_cast<const float4*>(base + r1 + H_ * W_);
        const float4 a13 = *reinterpret_cast<const float4*>(base + r1 + H_ * W_ + W_);

        float m0x = fmaxf(fmaxf(a00.x, a01.x), fmaxf(a02.x, a03.x));
        float m0y = fmaxf(fmaxf(a00.y, a01.y), fmaxf(a02.y, a03.y));
        float m0z = fmaxf(fmaxf(a00.z, a01.z), fmaxf(a02.z, a03.z));
        float m0w = fmaxf(fmaxf(a00.w, a01.w), fmaxf(a02.w, a03.w));
        float m1x = fmaxf(fmaxf(a10.x, a11.x), fmaxf(a12.x, a13.x));
        float m1y = fmaxf(fmaxf(a10.y, a11.y), fmaxf(a12.y, a13.y));
        float m1z = fmaxf(fmaxf(a10.z, a11.z), fmaxf(a12.z, a13.z));
        float m1w = fmaxf(fmaxf(a10.w, a11.w), fmaxf(a12.w, a13.w));

        acc += fmaxf(m0x, m0y) + fmaxf(m0z, m0w)
             + fmaxf(m1x, m1y) + fmaxf(m1z, m1w);
    }

    // Block reduction: warp shuffle, then smem across 8 warps.
    #pragma unroll
    for (int off = 16; off > 0; off >>= 1)
        acc += __shfl_xor_sync(0xFFFFFFFFu, acc, off);

    __shared__ float warp_sums[8];
    const int warp = tid >> 5;
    const int lane = tid & 31;
    if (lane == 0) warp_sums[warp] = acc;
    __syncthreads();

    if (warp == 0) {
        float v = (lane < 8) ? warp_sums[lane] : 0.0f;
        #pragma unroll
        for (int off = 4; off > 0; off >>= 1)
            v += __shfl_xor_sync(0xFFFFFFFFu, v, off);

        if (lane == 0) {
            atomicAdd(&g_scratch[n], v);
            __threadfence();
            // atomicInc wraps old==BLOCKS_PER_N-1 -> 0, so the counter is
            // automatically reset for the next launch/replay.
            unsigned int prev = atomicInc(&g_count[n], BLOCKS_PER_N - 1);
            if (prev == BLOCKS_PER_N - 1) {
                // Last block for this n: read+reset scratch, add bias sum.
                float total = atomicExch(&g_scratch[n], 0.0f);
                float bsum = 0.0f;
                #pragma unroll
                for (int cc = 0; cc < C_; ++cc)
                    bsum += __ldg(&bias[cc]);
                out[n] = total * SCALE_ + bsum;
            }
        }
    }
}

extern "C" void kernel_launch(void* const* d_in, const int* in_sizes, int n_in,
                              void* d_out, int out_size) {
    const float* o    = (const float*)d_in[0];
    const float* bias = (const float*)d_in[1];
    float* out = (float*)d_out;

    dim3 grid(BLOCKS_PER_N, N_);   // 64 x 16 = 1024 blocks, single wave
    fused_pool_reduce_kernel<<<grid, 256>>>(o, bias, out);
}